// round 13
// baseline (speedup 1.0000x reference)
#include <cuda_runtime.h>
#include <cuda_fp16.h>
#include <math.h>
#include <stdint.h>

// ---------------- problem constants ----------------
#define C_    512
#define SLAB  131072            // 256*512

// ---------------- device scratch ----------------
__device__ __align__(256) float g_att[16777216];    // [loc][i][j] fp32 scores
__device__ float g_nsum[256];
__device__ float g_nsumsq[256];

__device__ __align__(256) __half g_xh[33554432];    // x fp16 [t][n][pix][ic]
__device__ __align__(256) __half g_vh[33554432];    // virt post-GN fp16 [t][n][pix][ic]
__device__ __align__(256) __half g_virt16[33554432];// virt pre-GN fp16 [loc][n][c]
__device__ __align__(256) __half g_qh[33554432];    // q fp16 [loc][n][c]
__device__ __align__(256) __half g_kh[33554432];    // k fp16 [loc][n][c]
__device__ __align__(256) __half g_vT[33554432];    // v fp16 [loc][c][n]
__device__ __align__(256) __half g_att16[16777216]; // softmaxed att fp16 [loc][i][j]
__device__ __align__(256) __half g_wq[7077888];     // [tap][ocp(1536)][ic]
__device__ __align__(256) __half g_wc[2359296];     // [tap][oc][ic]

// ---------------- asm helpers ----------------
__device__ __forceinline__ uint32_t smem_u32_of(const void* p) {
    uint32_t a;
    asm("{ .reg .u64 t; cvta.to.shared.u64 t, %1; cvt.u32.u64 %0, t; }" : "=r"(a) : "l"(p));
    return a;
}
#define CPA(dst, src, sz) \
    asm volatile("cp.async.cg.shared.global [%0], [%1], 16, %2;" \
        :: "r"(dst), "l"(src), "r"(sz) : "memory")
#define CPA_COMMIT() asm volatile("cp.async.commit_group;" ::: "memory")
#define CPA_WAIT2() asm volatile("cp.async.wait_group 2;" ::: "memory")
#define CPA_WAIT1() asm volatile("cp.async.wait_group 1;" ::: "memory")
#define CPA_WAIT0() asm volatile("cp.async.wait_group 0;" ::: "memory")

__device__ __forceinline__ void ldsm4(uint32_t r[4], uint32_t addr) {
    asm volatile("ldmatrix.sync.aligned.m8n8.x4.shared.b16 {%0,%1,%2,%3}, [%4];"
        : "=r"(r[0]), "=r"(r[1]), "=r"(r[2]), "=r"(r[3]) : "r"(addr));
}
__device__ __forceinline__ void mma16816(float c[4], const uint32_t a[4],
                                         uint32_t b0, uint32_t b1) {
    asm volatile(
        "mma.sync.aligned.m16n8k16.row.col.f32.f16.f16.f32 "
        "{%0,%1,%2,%3}, {%4,%5,%6,%7}, {%8,%9}, {%0,%1,%2,%3};"
        : "+f"(c[0]), "+f"(c[1]), "+f"(c[2]), "+f"(c[3])
        : "r"(a[0]), "r"(a[1]), "r"(a[2]), "r"(a[3]), "r"(b0), "r"(b1));
}

// ---------------- MMA stage (128x128 tile, 8 warps 64x32), plain B ----------------
__device__ __forceinline__ void mma_stage(float acc[4][4][4], uint32_t aB, uint32_t bB,
                                          int lane, int wm, int wn) {
#pragma unroll
    for (int ks = 0; ks < 4; ks++) {
        uint32_t Af[4][4];
#pragma unroll
        for (int mf = 0; mf < 4; mf++) {
            int r = wm * 64 + mf * 16 + (lane & 7) + ((lane >> 3) & 1) * 8;
            int kc = ks * 2 + (lane >> 4);
            ldsm4(Af[mf], aB + r * 128 + 16 * (kc ^ (r & 7)));
        }
#pragma unroll
        for (int nb2 = 0; nb2 < 2; nb2++) {
            uint32_t Bf[4];
            int r = wn * 32 + nb2 * 16 + (lane & 7) + ((lane >> 4) << 3);
            int kc = ks * 2 + ((lane >> 3) & 1);
            ldsm4(Bf, bB + r * 128 + 16 * (kc ^ (r & 7)));
#pragma unroll
            for (int mf = 0; mf < 4; mf++) {
                mma16816(acc[mf][nb2 * 2 + 0], Af[mf], Bf[0], Bf[1]);
                mma16816(acc[mf][nb2 * 2 + 1], Af[mf], Bf[2], Bf[3]);
            }
        }
    }
}

// conv variant (64x32 warp tiles): shifted X view (row 128 = zeros)
__device__ __forceinline__ void mma_stage_conv(float acc[4][4][4], uint32_t aB, uint32_t xB,
                                               int lane, int wm, int wn, int dh, int dw) {
#pragma unroll
    for (int ks = 0; ks < 4; ks++) {
        uint32_t Af[4][4];
#pragma unroll
        for (int mf = 0; mf < 4; mf++) {
            int r = wm * 64 + mf * 16 + (lane & 7) + ((lane >> 3) & 1) * 8;
            int kc = ks * 2 + (lane >> 4);
            ldsm4(Af[mf], aB + r * 128 + 16 * (kc ^ (r & 7)));
        }
#pragma unroll
        for (int nb2 = 0; nb2 < 2; nb2++) {
            uint32_t Bf[4];
            int rj = wn * 32 + nb2 * 16 + (lane & 7) + ((lane >> 4) << 3);
            int p = rj & 63, n = rj >> 6;
            int hh = (p >> 3) + dh, ww = (p & 7) + dw;
            bool ok = ((unsigned)hh < 8u) && ((unsigned)ww < 8u);
            int row = ok ? ((n << 6) + (hh << 3) + ww) : 128;
            int kc = ks * 2 + ((lane >> 3) & 1);
            ldsm4(Bf, xB + row * 128 + 16 * (kc ^ (row & 7)));
#pragma unroll
            for (int mf = 0; mf < 4; mf++) {
                mma16816(acc[mf][nb2 * 2 + 0], Af[mf], Bf[0], Bf[1]);
                mma16816(acc[mf][nb2 * 2 + 1], Af[mf], Bf[2], Bf[3]);
            }
        }
    }
}

// ---------------- prepack ----------------
__global__ __launch_bounds__(256) void pack_x_kernel(const float* __restrict__ x) {
    __shared__ float sT[64 * 65];
    int icb = blockIdx.x, nt = blockIdx.y;
    int n = nt >> 2, t = nt & 3;
    int ic0 = icb * 64, tid = threadIdx.x;
#pragma unroll 4
    for (int rep = 0; rep < 16; rep++) {
        int e = rep * 256 + tid;
        int i = e >> 6, p = e & 63;
        sT[i * 65 + p] = x[(((size_t)n * C_ + ic0 + i) * 4 + t) * 64 + p];
    }
    __syncthreads();
#pragma unroll 4
    for (int rep = 0; rep < 16; rep++) {
        int e = rep * 256 + tid;
        int p = e >> 6, i = e & 63;
        g_xh[(size_t)t * 8388608 + (size_t)n * 32768 + (size_t)p * 512 + ic0 + i] =
            __float2half_rn(sT[i * 65 + p]);
    }
}

__global__ __launch_bounds__(256) void pack_w_kernel(const float* __restrict__ wq,
                                                     const float* __restrict__ wk,
                                                     const float* __restrict__ wv,
                                                     const float* __restrict__ wc) {
    int idx = blockIdx.x * 256 + threadIdx.x;
    if (idx < 7077888) {
        int ic = idx & 511, ocp = (idx >> 9) % 1536, tap = idx / (1536 * 512);
        const float* src = (ocp < 512) ? wq : (ocp < 1024) ? wk : wv;
        int oc = ocp & 511;
        g_wq[idx] = __float2half_rn(src[((size_t)oc * 512 + ic) * 9 + tap]);
    } else {
        int j = idx - 7077888;
        if (j < 2359296) {
            int ic = j & 511, oc = (j >> 9) & 511, tap = j >> 18;
            g_wc[j] = __float2half_rn(wc[((size_t)oc * 512 + ic) * 9 + tap]);
        }
    }
}

// ============ qkv conv: 320 threads, 10 warps of 64x64, CTA tile 320oc x 128pix =====
#define QSM_A   0                       // 3 x 40960
#define QSM_X   122880                  // 2 x 16640
#define QSM_TOT (122880 + 2 * 16640)    // 156160

__global__ __launch_bounds__(320, 1) void hconv_qkv_kernel() {
    float acc[4][8][4];
#pragma unroll
    for (int a = 0; a < 4; a++)
#pragma unroll
        for (int b = 0; b < 8; b++)
#pragma unroll
            for (int c = 0; c < 4; c++) acc[a][b][c] = 0.f;

    extern __shared__ char smem[];
    const uint32_t smem_b = smem_u32_of(smem);
    const int tid = threadIdx.x;
    const int lane = tid & 31, wid = tid >> 5;
    const int wm = wid >> 1, wn = wid & 1;          // 5 x 2 warps

    const int mt = blockIdx.y, y = blockIdx.x;      // mt 0..4, y 0..511
    const int t = y >> 7, n0 = (y & 127) * 2;
    const int oc0 = mt * 320;
    const size_t xbase = (size_t)t * 8388608;

    if (tid < 64) {   // zero halo rows (row 128 of both X buffers)
        int b = tid >> 5, c = tid & 31;
        *(float*)(smem + QSM_X + b * 16640 + 128 * 128 + c * 4) = 0.f;
    }

    auto loadA = [&](int s) {
        int tap = s % 9;
        uint32_t ab = smem_b + QSM_A + (s % 3) * 40960;
#pragma unroll
        for (int kk = 0; kk < 8; kk++) {
            int q = tid + kk * 320;
            int r = q >> 3, c = q & 7;
            int gr = oc0 + r; if (gr > 1535) gr = 1535;   // clamp partial tile (mt=4)
            const __half* src = g_wq +
                ((size_t)(tap * 1536 + gr)) * 512 + (s / 9) * 64 + c * 8;
            CPA(ab + r * 128 + 16 * (c ^ (r & 7)), src, 16);
        }
    };
    auto loadX = [&](int icb) {
        uint32_t xb = smem_b + QSM_X + (icb & 1) * 16640;
#pragma unroll
        for (int kk = 0; kk < 4; kk++) {
            int q = tid + kk * 320;
            if (q < 1024) {
                int r = q >> 3, c = q & 7;
                int n = n0 + (r >> 6), p = r & 63;
                const __half* src = g_xh + xbase + (size_t)p * 512 +
                    (size_t)n * 32768 + icb * 64 + c * 8;
                CPA(xb + r * 128 + 16 * (c ^ (r & 7)), src, 16);
            }
        }
    };

    loadA(0); loadX(0); CPA_COMMIT();
    loadA(1); CPA_COMMIT();

    for (int s = 0; s < 72; s++) {
        CPA_WAIT1();
        __syncthreads();
        if (s + 2 < 72) loadA(s + 2);
        if ((s % 9) == 0 && (s / 9) < 7) loadX(s / 9 + 1);
        CPA_COMMIT();
        const int tap = s % 9;
        const int dh = tap / 3 - 1, dw = tap % 3 - 1;
        const uint32_t aB = smem_b + QSM_A + (s % 3) * 40960;
        const uint32_t xB = smem_b + QSM_X + ((s / 9) & 1) * 16640;
#pragma unroll
        for (int ks = 0; ks < 4; ks++) {
            uint32_t Af[4][4];
#pragma unroll
            for (int mf = 0; mf < 4; mf++) {
                int r = wm * 64 + mf * 16 + (lane & 7) + ((lane >> 3) & 1) * 8;
                int kc = ks * 2 + (lane >> 4);
                ldsm4(Af[mf], aB + r * 128 + 16 * (kc ^ (r & 7)));
            }
#pragma unroll
            for (int nb2 = 0; nb2 < 4; nb2++) {
                uint32_t Bf[4];
                int rj = wn * 64 + nb2 * 16 + (lane & 7) + ((lane >> 4) << 3);
                int p = rj & 63;
                int hh = (p >> 3) + dh, ww = (p & 7) + dw;
                bool ok = ((unsigned)hh < 8u) && ((unsigned)ww < 8u);
                int row = ok ? ((rj & ~63) + (hh << 3) + ww) : 128;
                int kc = ks * 2 + ((lane >> 3) & 1);
                ldsm4(Bf, xB + row * 128 + 16 * (kc ^ (row & 7)));
#pragma unroll
                for (int mf = 0; mf < 4; mf++) {
                    mma16816(acc[mf][nb2 * 2 + 0], Af[mf], Bf[0], Bf[1]);
                    mma16816(acc[mf][nb2 * 2 + 1], Af[mf], Bf[2], Bf[3]);
                }
            }
        }
    }

    // epilogue: q,k -> [loc][n][c]; v -> [loc][c][n]; guard partial tile
#pragma unroll
    for (int mf = 0; mf < 4; mf++)
#pragma unroll
        for (int nb = 0; nb < 8; nb++)
#pragma unroll
            for (int pr = 0; pr < 2; pr++) {
                int ocp = oc0 + wm * 64 + mf * 16 + (lane >> 2) + pr * 8;
                if (ocp < 1536) {
                    int kind = ocp >> 9;
                    int oc = ocp & 511;
#pragma unroll
                    for (int e = 0; e < 2; e++) {
                        int j = wn * 64 + nb * 8 + (lane & 3) * 2 + e;
                        int n = n0 + (j >> 6), p = j & 63;
                        __half hv = __float2half_rn(acc[mf][nb][pr * 2 + e]);
                        size_t loc = (size_t)(t * 64 + p);
                        if (kind == 2)
                            g_vT[loc * 131072 + (size_t)oc * 256 + n] = hv;
                        else if (kind == 1)
                            g_kh[loc * 131072 + (size_t)n * 512 + oc] = hv;
                        else
                            g_qh[loc * 131072 + (size_t)n * 512 + oc] = hv;
                    }
                }
            }
}

// ---------------- out conv: proven 2-CTA 64x32 core (packed vh input) ----------------
#define CSM_A   0
#define CSM_X   65536
#define CSM_TOT (65536 + 2 * 16640)     // 98816

__global__ __launch_bounds__(256, 2) void hconv_out_kernel(const float* __restrict__ x,
                                                           float* __restrict__ out) {
    float acc[4][4][4];
#pragma unroll
    for (int a = 0; a < 4; a++)
#pragma unroll
        for (int b = 0; b < 4; b++)
#pragma unroll
            for (int c = 0; c < 4; c++) acc[a][b][c] = 0.f;

    extern __shared__ char smem[];
    const uint32_t smem_b = smem_u32_of(smem);
    const int tid = threadIdx.x;
    const int lane = tid & 31, wid = tid >> 5;
    const int wm = wid >> 2, wn = wid & 3;

    const int mt = blockIdx.y, y = blockIdx.x;     // y 0..511, mt 0..3
    const int t = y >> 7, n0 = (y & 127) * 2;
    const int oc0 = mt * 128;

    if (tid < 64) {
        int b = tid >> 5, c = tid & 31;
        *(float*)(smem + CSM_X + b * 16640 + 128 * 128 + c * 4) = 0.f;
    }

    auto loadA = [&](int s) {
        int tap = s % 9;
        uint32_t ab = smem_b + CSM_A + (s & 3) * 16384;
#pragma unroll
        for (int kk = 0; kk < 4; kk++) {
            int q = tid + kk * 256;
            int r = q >> 3, c = q & 7;
            const __half* src = g_wc +
                ((size_t)(tap * 512 + oc0 + r)) * 512 + (s / 9) * 64 + c * 8;
            CPA(ab + r * 128 + 16 * (c ^ (r & 7)), src, 16);
        }
    };
    auto loadX = [&](int icb) {
        uint32_t xb = smem_b + CSM_X + (icb & 1) * 16640;
#pragma unroll
        for (int kk = 0; kk < 4; kk++) {
            int q = tid + kk * 256;
            int r = q >> 3, c = q & 7;
            int n = n0 + (r >> 6), p = r & 63;
            const __half* src = g_vh + (size_t)t * 8388608 + (size_t)p * 512 +
                (size_t)n * 32768 + icb * 64 + c * 8;
            CPA(xb + r * 128 + 16 * (c ^ (r & 7)), src, 16);
        }
    };

    loadA(0); loadX(0); CPA_COMMIT();
    loadA(1); CPA_COMMIT();
    loadA(2); CPA_COMMIT();

    for (int s = 0; s < 72; s++) {
        CPA_WAIT2();
        __syncthreads();
        if (s + 3 < 72) loadA(s + 3);
        if ((s % 9) == 0 && (s / 9) < 7) loadX(s / 9 + 1);
        CPA_COMMIT();
        int tap = s % 9;
        mma_stage_conv(acc, smem_b + CSM_A + (s & 3) * 16384,
                       smem_b + CSM_X + ((s / 9) & 1) * 16640,
                       lane, wm, wn, tap / 3 - 1, tap % 3 - 1);
    }

#pragma unroll
    for (int mf = 0; mf < 4; mf++)
#pragma unroll
        for (int nb = 0; nb < 4; nb++)
#pragma unroll
            for (int pr = 0; pr < 2; pr++) {
                int oc = oc0 + wm * 64 + mf * 16 + (lane >> 2) + pr * 8;
#pragma unroll
                for (int e = 0; e < 2; e++) {
                    int j = wn * 32 + nb * 8 + (lane & 3) * 2 + e;
                    int n = n0 + (j >> 6), p = j & 63;
                    size_t gi = (((size_t)n * 512 + oc) * 4 + t) * 64 + p;
                    out[gi] = x[gi] + acc[mf][nb][pr * 2 + e];
                }
            }
}

// ---------------- attention scores (HMMA): S = scale*q.k^T masked -> fp32 ----------
__global__ __launch_bounds__(256, 2) void attn_scores_tc(const int* __restrict__ roi) {
    float acc[4][4][4];
#pragma unroll
    for (int a = 0; a < 4; a++)
#pragma unroll
        for (int b = 0; b < 4; b++)
#pragma unroll
            for (int c = 0; c < 4; c++) acc[a][b][c] = 0.f;

    extern __shared__ char smem[];
    const uint32_t smem_b = smem_u32_of(smem);
    const int tid = threadIdx.x, lane = tid & 31, wid = tid >> 5;
    const int wm = wid >> 2, wn = wid & 3;
    const int loc = blockIdx.y;
    const int i0 = (blockIdx.x >> 1) * 128, j0 = (blockIdx.x & 1) * 128;
    const __half* qb = g_qh + (size_t)loc * 131072;
    const __half* kb = g_kh + (size_t)loc * 131072;

    auto load = [&](int s) {
        uint32_t ab = smem_b + (s % 3) * 32768;
#pragma unroll
        for (int kk = 0; kk < 8; kk++) {
            int task = tid + kk * 256;
            int reg = task >> 10, q2 = task & 1023;
            int r = q2 >> 3, c = q2 & 7;
            const __half* src = (reg == 0)
                ? qb + (size_t)(i0 + r) * 512 + s * 64 + c * 8
                : kb + (size_t)(j0 + r) * 512 + s * 64 + c * 8;
            CPA(ab + reg * 16384 + r * 128 + 16 * (c ^ (r & 7)), src, 16);
        }
        CPA_COMMIT();
    };
    load(0); load(1);
    for (int s = 0; s < 8; s++) {
        if (s < 7) CPA_WAIT1(); else CPA_WAIT0();
        __syncthreads();
        if (s + 2 < 8) load(s + 2);
        uint32_t ab = smem_b + (s % 3) * 32768;
        mma_stage(acc, ab, ab + 16384, lane, wm, wn);
        __syncthreads();
    }
    const float scale = 0.044194173824159216f;
    float* outp = g_att + (size_t)loc * 65536;
#pragma unroll
    for (int mf = 0; mf < 4; mf++)
#pragma unroll
        for (int pr = 0; pr < 2; pr++) {
            int i = i0 + wm * 64 + mf * 16 + (lane >> 2) + pr * 8;
            int ri = __ldg(&roi[i]);
#pragma unroll
            for (int nb = 0; nb < 4; nb++) {
                int j = j0 + wn * 32 + nb * 8 + (lane & 3) * 2;
                float2 v;
                v.x = (ri == __ldg(&roi[j]))     ? acc[mf][nb][pr * 2 + 0] * scale : -1e30f;
                v.y = (ri == __ldg(&roi[j + 1])) ? acc[mf][nb][pr * 2 + 1] * scale : -1e30f;
                *(float2*)&outp[(size_t)i * 256 + j] = v;
            }
        }
}

// ---------------- softmax (fp32 in, fp16 out) + zero GN accumulators ----------------
__global__ __launch_bounds__(256) void softmax_kernel() {
    if (blockIdx.x == 0) {
        g_nsum[threadIdx.x] = 0.f;
        g_nsumsq[threadIdx.x] = 0.f;
    }
    int row = blockIdx.x * 8 + (threadIdx.x >> 5);
    int lane = threadIdx.x & 31;
    const float4* base = (const float4*)(g_att + (size_t)row * 256);
    float4 v0 = base[lane];
    float4 v1 = base[lane + 32];
    float m = fmaxf(fmaxf(fmaxf(v0.x, v0.y), fmaxf(v0.z, v0.w)),
                    fmaxf(fmaxf(v1.x, v1.y), fmaxf(v1.z, v1.w)));
#pragma unroll
    for (int o = 16; o; o >>= 1) m = fmaxf(m, __shfl_xor_sync(0xffffffffu, m, o));
    v0.x = expf(v0.x - m); v0.y = expf(v0.y - m); v0.z = expf(v0.z - m); v0.w = expf(v0.w - m);
    v1.x = expf(v1.x - m); v1.y = expf(v1.y - m); v1.z = expf(v1.z - m); v1.w = expf(v1.w - m);
    float s = v0.x + v0.y + v0.z + v0.w + v1.x + v1.y + v1.z + v1.w;
#pragma unroll
    for (int o = 16; o; o >>= 1) s += __shfl_xor_sync(0xffffffffu, s, o);
    float inv = 1.f / s;
    __half2* ob = (__half2*)(g_att16 + (size_t)row * 256);
    ob[lane * 2 + 0] = __floats2half2_rn(v0.x * inv, v0.y * inv);
    ob[lane * 2 + 1] = __floats2half2_rn(v0.z * inv, v0.w * inv);
    ob[(lane + 32) * 2 + 0] = __floats2half2_rn(v1.x * inv, v1.y * inv);
    ob[(lane + 32) * 2 + 1] = __floats2half2_rn(v1.z * inv, v1.w * inv);
}

// ---------------- virt = att @ v (HMMA) -> g_virt16 fp16 + GN partial sums ----------
__global__ __launch_bounds__(256, 2) void attn_v_tc() {
    float acc[4][4][4];
#pragma unroll
    for (int a = 0; a < 4; a++)
#pragma unroll
        for (int b = 0; b < 4; b++)
#pragma unroll
            for (int c = 0; c < 4; c++) acc[a][b][c] = 0.f;

    extern __shared__ char smem[];
    const uint32_t smem_b = smem_u32_of(smem);
    const int tid = threadIdx.x, lane = tid & 31, wid = tid >> 5;
    const int wm = wid >> 2, wn = wid & 3;
    const int loc = blockIdx.y;
    const int i0 = (blockIdx.x >> 2) * 128, c0 = (blockIdx.x & 3) * 128;
    const __half* ab_g = g_att16 + (size_t)loc * 65536;
    const __half* bb_g = g_vT + (size_t)loc * 131072;

    auto load = [&](int s) {
        uint32_t ab = smem_b + (s % 3) * 32768;
#pragma unroll
        for (int kk = 0; kk < 8; kk++) {
            int task = tid + kk * 256;
            int reg = task >> 10, q2 = task & 1023;
            int r = q2 >> 3, c = q2 & 7;
            const __half* src = (reg == 0)
                ? ab_g + (size_t)(i0 + r) * 256 + s * 64 + c * 8
                : bb_g + (size_t)(c0 + r) * 256 + s * 64 + c * 8;
            CPA(ab + reg * 16384 + r * 128 + 16 * (c ^ (r & 7)), src, 16);
        }
        CPA_COMMIT();
    };
    load(0); load(1);
    for (int s = 0; s < 4; s++) {
        if (s < 3) CPA_WAIT1(); else CPA_WAIT0();
        __syncthreads();
        if (s + 2 < 4) load(s + 2);
        uint32_t ab = smem_b + (s % 3) * 32768;
        mma_stage(acc, ab, ab + 16384, lane, wm, wn);
        __syncthreads();
    }
    __half* outp = g_virt16 + (size_t)loc * 131072;
#pragma unroll
    for (int mf = 0; mf < 4; mf++)
#pragma unroll
        for (int pr = 0; pr < 2; pr++) {
            int i = i0 + wm * 64 + mf * 16 + (lane >> 2) + pr * 8;
            float s = 0.f, sq = 0.f;
#pragma unroll
            for (int nb = 0; nb < 4; nb++) {
                float a0 = acc[mf][nb][pr * 2 + 0];
                float a1 = acc[mf][nb][pr * 2 + 1];
                s += a0 + a1;
                sq += a0 * a0 + a1 * a1;
                int cc = c0 + wn * 32 + nb * 8 + (lane & 3) * 2;
                *(__half2*)&outp[(size_t)i * 512 + cc] = __floats2half2_rn(a0, a1);
            }
            s  += __shfl_xor_sync(0xffffffffu, s, 1);
            s  += __shfl_xor_sync(0xffffffffu, s, 2);
            sq += __shfl_xor_sync(0xffffffffu, sq, 1);
            sq += __shfl_xor_sync(0xffffffffu, sq, 2);
            if ((lane & 3) == 0) {
                atomicAdd(&g_nsum[i], s);
                atomicAdd(&g_nsumsq[i], sq);
            }
        }
}

// ---------------- GroupNorm normalize (+relu) -> packed fp16 [t][n][pix][ic] --------
__global__ __launch_bounds__(256) void gn_norm_kernel(const float* __restrict__ gamma,
                                                      const float* __restrict__ beta) {
    size_t i2 = (size_t)blockIdx.x * 256 + threadIdx.x;
    size_t i = i2 * 2;                      // index into g_virt16 [loc][n][c]
    int c = (int)(i & 511);
    int n = (int)((i >> 9) & 255);
    int loc = (int)(i >> 17);
    int t = loc >> 6, p = loc & 63;
    const float inv = 1.f / 131072.f;
    float mu = g_nsum[n] * inv;
    float var = g_nsumsq[n] * inv - mu * mu;
    float rstd = rsqrtf(var + 1e-5f);
    float2 vv = __half22float2(*(const __half2*)&g_virt16[i]);
    float a = fmaxf((vv.x - mu) * rstd * gamma[c] + beta[c], 0.f);
    float b = fmaxf((vv.y - mu) * rstd * gamma[c + 1] + beta[c + 1], 0.f);
    size_t dst = (size_t)t * 8388608 + (size_t)n * 32768 + (size_t)p * 512 + c;
    *(__half2*)&g_vh[dst] = __floats2half2_rn(a, b);
}

// ---------------- launch ----------------
extern "C" void kernel_launch(void* const* d_in, const int* in_sizes, int n_in,
                              void* d_out, int out_size) {
    const float* x     = (const float*)d_in[0];
    const int*   roi   = (const int*)d_in[1];
    const float* Wq    = (const float*)d_in[2];
    const float* Wk    = (const float*)d_in[3];
    const float* Wv    = (const float*)d_in[4];
    const float* Wc    = (const float*)d_in[5];
    const float* gamma = (const float*)d_in[6];
    const float* beta  = (const float*)d_in[7];
    float* out = (float*)d_out;

    cudaFuncSetAttribute(hconv_qkv_kernel, cudaFuncAttributeMaxDynamicSharedMemorySize, QSM_TOT);
    cudaFuncSetAttribute(hconv_out_kernel, cudaFuncAttributeMaxDynamicSharedMemorySize, CSM_TOT);
    cudaFuncSetAttribute(attn_scores_tc, cudaFuncAttributeMaxDynamicSharedMemorySize, 98304);
    cudaFuncSetAttribute(attn_v_tc, cudaFuncAttributeMaxDynamicSharedMemorySize, 98304);

    pack_x_kernel<<<dim3(8, 1024), 256>>>(x);
    pack_w_kernel<<<36864, 256>>>(Wq, Wk, Wv, Wc);

    hconv_qkv_kernel<<<dim3(512, 5), 320, QSM_TOT>>>();

    attn_scores_tc<<<dim3(4, 256), 256, 98304>>>(roi);
    softmax_kernel<<<8192, 256>>>();
    attn_v_tc<<<dim3(8, 256), 256, 98304>>>();

    gn_norm_kernel<<<65536, 256>>>(gamma, beta);

    hconv_out_kernel<<<dim3(512, 4), 256, CSM_TOT>>>(x, out);
}

// round 14
// speedup vs baseline: 1.3665x; 1.3665x over previous
#include <cuda_runtime.h>
#include <cuda_fp16.h>
#include <math.h>
#include <stdint.h>

// ---------------- problem constants ----------------
#define C_    512
#define SLAB  131072            // 256*512

// ---------------- device scratch ----------------
__device__ __align__(256) float g_att[16777216];    // [loc][i][j] fp32 scores
__device__ float g_nsum[256];
__device__ float g_nsumsq[256];

__device__ __align__(256) __half g_xh[33554432];    // x fp16 [t][n][pix][ic]
__device__ __align__(256) __half g_vh[33554432];    // v (pre-attn) THEN virt post-GN fp16 [loc][n][c]
__device__ __align__(256) __half g_virt16[33554432];// virt pre-GN fp16 [loc][n][c]
__device__ __align__(256) __half g_qh[33554432];    // q fp16 [loc][n][c]
__device__ __align__(256) __half g_kh[33554432];    // k fp16 [loc][n][c]
__device__ __align__(256) __half g_vT[33554432];    // v fp16 [loc][c][n]
__device__ __align__(256) __half g_att16[16777216]; // softmaxed att fp16 [loc][i][j]
__device__ __align__(256) __half g_wq[7077888];     // [tap][ocp(1536)][ic]
__device__ __align__(256) __half g_wc[2359296];     // [tap][oc][ic]

// ---------------- asm helpers ----------------
__device__ __forceinline__ uint32_t smem_u32_of(const void* p) {
    uint32_t a;
    asm("{ .reg .u64 t; cvta.to.shared.u64 t, %1; cvt.u32.u64 %0, t; }" : "=r"(a) : "l"(p));
    return a;
}
#define CPA(dst, src, sz) \
    asm volatile("cp.async.cg.shared.global [%0], [%1], 16, %2;" \
        :: "r"(dst), "l"(src), "r"(sz) : "memory")
// L1-cached variant for weight streams shared by co-resident CTAs
#define CPA_A(dst, src) \
    asm volatile("cp.async.ca.shared.global [%0], [%1], 16;" \
        :: "r"(dst), "l"(src) : "memory")
#define CPA_COMMIT() asm volatile("cp.async.commit_group;" ::: "memory")
#define CPA_WAIT2() asm volatile("cp.async.wait_group 2;" ::: "memory")
#define CPA_WAIT1() asm volatile("cp.async.wait_group 1;" ::: "memory")
#define CPA_WAIT0() asm volatile("cp.async.wait_group 0;" ::: "memory")

__device__ __forceinline__ void ldsm4(uint32_t r[4], uint32_t addr) {
    asm volatile("ldmatrix.sync.aligned.m8n8.x4.shared.b16 {%0,%1,%2,%3}, [%4];"
        : "=r"(r[0]), "=r"(r[1]), "=r"(r[2]), "=r"(r[3]) : "r"(addr));
}
__device__ __forceinline__ void mma16816(float c[4], const uint32_t a[4],
                                         uint32_t b0, uint32_t b1) {
    asm volatile(
        "mma.sync.aligned.m16n8k16.row.col.f32.f16.f16.f32 "
        "{%0,%1,%2,%3}, {%4,%5,%6,%7}, {%8,%9}, {%0,%1,%2,%3};"
        : "+f"(c[0]), "+f"(c[1]), "+f"(c[2]), "+f"(c[3])
        : "r"(a[0]), "r"(a[1]), "r"(a[2]), "r"(a[3]), "r"(b0), "r"(b1));
}

// ---------------- MMA stage (128x128 tile, 8 warps 64x32), plain B ----------------
__device__ __forceinline__ void mma_stage(float acc[4][4][4], uint32_t aB, uint32_t bB,
                                          int lane, int wm, int wn) {
#pragma unroll
    for (int ks = 0; ks < 4; ks++) {
        uint32_t Af[4][4];
#pragma unroll
        for (int mf = 0; mf < 4; mf++) {
            int r = wm * 64 + mf * 16 + (lane & 7) + ((lane >> 3) & 1) * 8;
            int kc = ks * 2 + (lane >> 4);
            ldsm4(Af[mf], aB + r * 128 + 16 * (kc ^ (r & 7)));
        }
#pragma unroll
        for (int nb2 = 0; nb2 < 2; nb2++) {
            uint32_t Bf[4];
            int r = wn * 32 + nb2 * 16 + (lane & 7) + ((lane >> 4) << 3);
            int kc = ks * 2 + ((lane >> 3) & 1);
            ldsm4(Bf, bB + r * 128 + 16 * (kc ^ (r & 7)));
#pragma unroll
            for (int mf = 0; mf < 4; mf++) {
                mma16816(acc[mf][nb2 * 2 + 0], Af[mf], Bf[0], Bf[1]);
                mma16816(acc[mf][nb2 * 2 + 1], Af[mf], Bf[2], Bf[3]);
            }
        }
    }
}

// conv variant (64x32 warp tiles): shifted X view (row 128 = zeros)
__device__ __forceinline__ void mma_stage_conv(float acc[4][4][4], uint32_t aB, uint32_t xB,
                                               int lane, int wm, int wn, int dh, int dw) {
#pragma unroll
    for (int ks = 0; ks < 4; ks++) {
        uint32_t Af[4][4];
#pragma unroll
        for (int mf = 0; mf < 4; mf++) {
            int r = wm * 64 + mf * 16 + (lane & 7) + ((lane >> 3) & 1) * 8;
            int kc = ks * 2 + (lane >> 4);
            ldsm4(Af[mf], aB + r * 128 + 16 * (kc ^ (r & 7)));
        }
#pragma unroll
        for (int nb2 = 0; nb2 < 2; nb2++) {
            uint32_t Bf[4];
            int rj = wn * 32 + nb2 * 16 + (lane & 7) + ((lane >> 4) << 3);
            int p = rj & 63, n = rj >> 6;
            int hh = (p >> 3) + dh, ww = (p & 7) + dw;
            bool ok = ((unsigned)hh < 8u) && ((unsigned)ww < 8u);
            int row = ok ? ((n << 6) + (hh << 3) + ww) : 128;
            int kc = ks * 2 + ((lane >> 3) & 1);
            ldsm4(Bf, xB + row * 128 + 16 * (kc ^ (row & 7)));
#pragma unroll
            for (int mf = 0; mf < 4; mf++) {
                mma16816(acc[mf][nb2 * 2 + 0], Af[mf], Bf[0], Bf[1]);
                mma16816(acc[mf][nb2 * 2 + 1], Af[mf], Bf[2], Bf[3]);
            }
        }
    }
}

// ---------------- prepack ----------------
__global__ __launch_bounds__(256) void pack_x_kernel(const float* __restrict__ x) {
    __shared__ float sT[64 * 65];
    int icb = blockIdx.x, nt = blockIdx.y;
    int n = nt >> 2, t = nt & 3;
    int ic0 = icb * 64, tid = threadIdx.x;
#pragma unroll 4
    for (int rep = 0; rep < 16; rep++) {
        int e = rep * 256 + tid;
        int i = e >> 6, p = e & 63;
        sT[i * 65 + p] = x[(((size_t)n * C_ + ic0 + i) * 4 + t) * 64 + p];
    }
    __syncthreads();
#pragma unroll 4
    for (int rep = 0; rep < 16; rep++) {
        int e = rep * 256 + tid;
        int p = e >> 6, i = e & 63;
        g_xh[(size_t)t * 8388608 + (size_t)n * 32768 + (size_t)p * 512 + ic0 + i] =
            __float2half_rn(sT[i * 65 + p]);
    }
}

__global__ __launch_bounds__(256) void pack_w_kernel(const float* __restrict__ wq,
                                                     const float* __restrict__ wk,
                                                     const float* __restrict__ wv,
                                                     const float* __restrict__ wc) {
    int idx = blockIdx.x * 256 + threadIdx.x;
    if (idx < 7077888) {
        int ic = idx & 511, ocp = (idx >> 9) % 1536, tap = idx / (1536 * 512);
        const float* src = (ocp < 512) ? wq : (ocp < 1024) ? wk : wv;
        int oc = ocp & 511;
        g_wq[idx] = __float2half_rn(src[((size_t)oc * 512 + ic) * 9 + tap]);
    } else {
        int j = idx - 7077888;
        if (j < 2359296) {
            int ic = j & 511, oc = (j >> 9) & 511, tap = j >> 18;
            g_wc[j] = __float2half_rn(wc[((size_t)oc * 512 + ic) * 9 + tap]);
        }
    }
}

// ---------------- conv core: A-stream (72 tiles, depth-4) + X-stream (8 tiles) ------
#define CSM_A   0
#define CSM_X   65536
#define CSM_TOT (65536 + 2 * 16640)     // 98816

struct ConvArgs {
    const __half* w; int ocw; int oc0;
    const __half* d; size_t base; int sq; int sn; int n0;
};

__device__ __forceinline__ void conv_core(float acc[4][4][4], const ConvArgs& A_) {
    extern __shared__ char smem[];
    const uint32_t smem_b = smem_u32_of(smem);
    const int tid = threadIdx.x;
    const int lane = tid & 31, wid = tid >> 5;
    const int wm = wid >> 2, wn = wid & 3;

    if (tid < 64) {   // zero halo rows (row 128 of both X buffers)
        int b = tid >> 5, c = tid & 31;
        *(float*)(smem + CSM_X + b * 16640 + 128 * 128 + c * 4) = 0.f;
    }

    auto loadA = [&](int s) {
        int tap = s % 9;
        uint32_t ab = smem_b + CSM_A + (s & 3) * 16384;
#pragma unroll
        for (int kk = 0; kk < 4; kk++) {
            int q = tid + kk * 256;
            int r = q >> 3, c = q & 7;
            const __half* src = A_.w +
                ((size_t)(tap * A_.ocw + A_.oc0 + r)) * 512 + (s / 9) * 64 + c * 8;
            CPA_A(ab + r * 128 + 16 * (c ^ (r & 7)), src);
        }
    };
    auto loadX = [&](int icb) {
        uint32_t xb = smem_b + CSM_X + (icb & 1) * 16640;
#pragma unroll
        for (int kk = 0; kk < 4; kk++) {
            int q = tid + kk * 256;
            int r = q >> 3, c = q & 7;
            int n = A_.n0 + (r >> 6), p = r & 63;
            const __half* src = A_.d + A_.base + (size_t)p * A_.sq +
                (size_t)n * A_.sn + icb * 64 + c * 8;
            CPA(xb + r * 128 + 16 * (c ^ (r & 7)), src, 16);
        }
    };

    loadA(0); loadX(0); CPA_COMMIT();
    loadA(1); CPA_COMMIT();
    loadA(2); CPA_COMMIT();

    for (int s = 0; s < 72; s++) {
        CPA_WAIT2();
        __syncthreads();
        // issue loads for stage s+3 into buffer freed by stage s-1 (guarded by sync)
        if (s + 3 < 72) loadA(s + 3);
        if ((s % 9) == 0 && (s / 9) < 7) loadX(s / 9 + 1);
        CPA_COMMIT();
        int tap = s % 9;
        mma_stage_conv(acc, smem_b + CSM_A + (s & 3) * 16384,
                       smem_b + CSM_X + ((s / 9) & 1) * 16640,
                       lane, wm, wn, tap / 3 - 1, tap % 3 - 1);
    }
}

// ------- conv qkv: epilogue -> q,k,v ALL coalesced fp16 [loc][n][c] (v into g_vh) ---
__global__ __launch_bounds__(256, 2) void hconv_qkv_kernel() {
    float acc[4][4][4];
#pragma unroll
    for (int a = 0; a < 4; a++)
#pragma unroll
        for (int b = 0; b < 4; b++)
#pragma unroll
            for (int c = 0; c < 4; c++) acc[a][b][c] = 0.f;

    const int mt = blockIdx.y, y = blockIdx.x;     // y 0..511, mt 0..11
    const int t = y >> 7, n0 = (y & 127) * 2;

    ConvArgs ar;
    ar.w = g_wq; ar.ocw = 1536; ar.oc0 = mt * 128;
    ar.d = g_xh; ar.base = (size_t)t * 8388608; ar.sq = 512; ar.sn = 32768; ar.n0 = n0;
    conv_core(acc, ar);

    const int lane = threadIdx.x & 31, wid = threadIdx.x >> 5;
    const int wm = wid >> 2, wn = wid & 3;
    const int kind = mt >> 2;             // 0=q 1=k 2=v
    const int ocb = (mt * 128) & 511;
    __half* dsth = (kind == 0) ? g_qh : (kind == 1) ? g_kh : g_vh;
#pragma unroll
    for (int mf = 0; mf < 4; mf++)
#pragma unroll
        for (int nb = 0; nb < 4; nb++)
#pragma unroll
            for (int pr = 0; pr < 2; pr++) {
                int oc = ocb + wm * 64 + mf * 16 + (lane >> 2) + pr * 8;
#pragma unroll
                for (int e = 0; e < 2; e++) {
                    int j = wn * 32 + nb * 8 + (lane & 3) * 2 + e;
                    int n = n0 + (j >> 6), p = j & 63;
                    size_t loc = (size_t)(t * 64 + p);
                    dsth[loc * 131072 + (size_t)n * 512 + oc] =
                        __float2half_rn(acc[mf][nb][pr * 2 + e]);
                }
            }
}

// ---------------- v transpose: g_vh [loc][n][c] -> g_vT [loc][c][n] ----------------
__global__ __launch_bounds__(256) void vtrans_kernel() {
    __shared__ __half sT[64][72];
    const int loc = blockIdx.y;
    const int n0 = (blockIdx.x & 3) * 64, c0 = (blockIdx.x >> 2) * 64;
    const int tid = threadIdx.x;
#pragma unroll
    for (int pass = 0; pass < 2; pass++) {
        int e = pass * 256 + tid;
        int n = e >> 3, cc = (e & 7) * 8;
        uint4 u = *(const uint4*)&g_vh[(size_t)loc * 131072 + (size_t)(n0 + n) * 512 + c0 + cc];
        const __half* h = (const __half*)&u;
#pragma unroll
        for (int i = 0; i < 8; i++) sT[cc + i][n] = h[i];
    }
    __syncthreads();
#pragma unroll
    for (int pass = 0; pass < 2; pass++) {
        int e = pass * 256 + tid;
        int c = e >> 3, nn = (e & 7) * 8;
        *(uint4*)&g_vT[(size_t)loc * 131072 + (size_t)(c0 + c) * 256 + n0 + nn] =
            *(const uint4*)&sT[c][nn];
    }
}

// ---------------- conv out: out = x + conv(vh_postGN, Wc) ----------------
__global__ __launch_bounds__(256, 2) void hconv_out_kernel(const float* __restrict__ x,
                                                           float* __restrict__ out) {
    float acc[4][4][4];
#pragma unroll
    for (int a = 0; a < 4; a++)
#pragma unroll
        for (int b = 0; b < 4; b++)
#pragma unroll
            for (int c = 0; c < 4; c++) acc[a][b][c] = 0.f;

    const int mt = blockIdx.y, y = blockIdx.x;     // y 0..511, mt 0..3
    const int t = y >> 7, n0 = (y & 127) * 2;

    ConvArgs ar;
    ar.w = g_wc; ar.ocw = 512; ar.oc0 = mt * 128;
    ar.d = g_vh; ar.base = (size_t)t * 8388608; ar.sq = 131072; ar.sn = 512; ar.n0 = n0;
    conv_core(acc, ar);

    const int lane = threadIdx.x & 31, wid = threadIdx.x >> 5;
    const int wm = wid >> 2, wn = wid & 3;
    const int oc0 = mt * 128;
#pragma unroll
    for (int mf = 0; mf < 4; mf++)
#pragma unroll
        for (int nb = 0; nb < 4; nb++)
#pragma unroll
            for (int pr = 0; pr < 2; pr++) {
                int oc = oc0 + wm * 64 + mf * 16 + (lane >> 2) + pr * 8;
#pragma unroll
                for (int e = 0; e < 2; e++) {
                    int j = wn * 32 + nb * 8 + (lane & 3) * 2 + e;
                    int n = n0 + (j >> 6), p = j & 63;
                    size_t gi = (((size_t)n * 512 + oc) * 4 + t) * 64 + p;
                    out[gi] = x[gi] + acc[mf][nb][pr * 2 + e];
                }
            }
}

// ---------------- attention scores (HMMA): S = scale*q.k^T masked -> fp32 ----------
__global__ __launch_bounds__(256, 2) void attn_scores_tc(const int* __restrict__ roi) {
    float acc[4][4][4];
#pragma unroll
    for (int a = 0; a < 4; a++)
#pragma unroll
        for (int b = 0; b < 4; b++)
#pragma unroll
            for (int c = 0; c < 4; c++) acc[a][b][c] = 0.f;

    extern __shared__ char smem[];
    const uint32_t smem_b = smem_u32_of(smem);
    const int tid = threadIdx.x, lane = tid & 31, wid = tid >> 5;
    const int wm = wid >> 2, wn = wid & 3;
    const int loc = blockIdx.y;
    const int i0 = (blockIdx.x >> 1) * 128, j0 = (blockIdx.x & 1) * 128;
    const __half* qb = g_qh + (size_t)loc * 131072;
    const __half* kb = g_kh + (size_t)loc * 131072;

    auto load = [&](int s) {
        uint32_t ab = smem_b + (s % 3) * 32768;
#pragma unroll
        for (int kk = 0; kk < 8; kk++) {
            int task = tid + kk * 256;
            int reg = task >> 10, q2 = task & 1023;
            int r = q2 >> 3, c = q2 & 7;
            const __half* src = (reg == 0)
                ? qb + (size_t)(i0 + r) * 512 + s * 64 + c * 8
                : kb + (size_t)(j0 + r) * 512 + s * 64 + c * 8;
            CPA(ab + reg * 16384 + r * 128 + 16 * (c ^ (r & 7)), src, 16);
        }
        CPA_COMMIT();
    };
    load(0); load(1);
    for (int s = 0; s < 8; s++) {
        if (s < 7) CPA_WAIT1(); else CPA_WAIT0();
        __syncthreads();
        if (s + 2 < 8) load(s + 2);
        uint32_t ab = smem_b + (s % 3) * 32768;
        mma_stage(acc, ab, ab + 16384, lane, wm, wn);
        __syncthreads();
    }
    const float scale = 0.044194173824159216f;
    float* outp = g_att + (size_t)loc * 65536;
#pragma unroll
    for (int mf = 0; mf < 4; mf++)
#pragma unroll
        for (int pr = 0; pr < 2; pr++) {
            int i = i0 + wm * 64 + mf * 16 + (lane >> 2) + pr * 8;
            int ri = __ldg(&roi[i]);
#pragma unroll
            for (int nb = 0; nb < 4; nb++) {
                int j = j0 + wn * 32 + nb * 8 + (lane & 3) * 2;
                float2 v;
                v.x = (ri == __ldg(&roi[j]))     ? acc[mf][nb][pr * 2 + 0] * scale : -1e30f;
                v.y = (ri == __ldg(&roi[j + 1])) ? acc[mf][nb][pr * 2 + 1] * scale : -1e30f;
                *(float2*)&outp[(size_t)i * 256 + j] = v;
            }
        }
}

// ---------------- softmax (fp32 in, fp16 out) + zero GN accumulators ----------------
__global__ __launch_bounds__(256) void softmax_kernel() {
    if (blockIdx.x == 0) {
        g_nsum[threadIdx.x] = 0.f;
        g_nsumsq[threadIdx.x] = 0.f;
    }
    int row = blockIdx.x * 8 + (threadIdx.x >> 5);
    int lane = threadIdx.x & 31;
    const float4* base = (const float4*)(g_att + (size_t)row * 256);
    float4 v0 = base[lane];
    float4 v1 = base[lane + 32];
    float m = fmaxf(fmaxf(fmaxf(v0.x, v0.y), fmaxf(v0.z, v0.w)),
                    fmaxf(fmaxf(v1.x, v1.y), fmaxf(v1.z, v1.w)));
#pragma unroll
    for (int o = 16; o; o >>= 1) m = fmaxf(m, __shfl_xor_sync(0xffffffffu, m, o));
    v0.x = expf(v0.x - m); v0.y = expf(v0.y - m); v0.z = expf(v0.z - m); v0.w = expf(v0.w - m);
    v1.x = expf(v1.x - m); v1.y = expf(v1.y - m); v1.z = expf(v1.z - m); v1.w = expf(v1.w - m);
    float s = v0.x + v0.y + v0.z + v0.w + v1.x + v1.y + v1.z + v1.w;
#pragma unroll
    for (int o = 16; o; o >>= 1) s += __shfl_xor_sync(0xffffffffu, s, o);
    float inv = 1.f / s;
    __half2* ob = (__half2*)(g_att16 + (size_t)row * 256);
    ob[lane * 2 + 0] = __floats2half2_rn(v0.x * inv, v0.y * inv);
    ob[lane * 2 + 1] = __floats2half2_rn(v0.z * inv, v0.w * inv);
    ob[(lane + 32) * 2 + 0] = __floats2half2_rn(v1.x * inv, v1.y * inv);
    ob[(lane + 32) * 2 + 1] = __floats2half2_rn(v1.z * inv, v1.w * inv);
}

// ---------------- virt = att @ v (HMMA) -> g_virt16 fp16 + GN partial sums ----------
__global__ __launch_bounds__(256, 2) void attn_v_tc() {
    float acc[4][4][4];
#pragma unroll
    for (int a = 0; a < 4; a++)
#pragma unroll
        for (int b = 0; b < 4; b++)
#pragma unroll
            for (int c = 0; c < 4; c++) acc[a][b][c] = 0.f;

    extern __shared__ char smem[];
    const uint32_t smem_b = smem_u32_of(smem);
    const int tid = threadIdx.x, lane = tid & 31, wid = tid >> 5;
    const int wm = wid >> 2, wn = wid & 3;
    const int loc = blockIdx.y;
    const int i0 = (blockIdx.x >> 2) * 128, c0 = (blockIdx.x & 3) * 128;
    const __half* ab_g = g_att16 + (size_t)loc * 65536;
    const __half* bb_g = g_vT + (size_t)loc * 131072;

    auto load = [&](int s) {
        uint32_t ab = smem_b + (s % 3) * 32768;
#pragma unroll
        for (int kk = 0; kk < 8; kk++) {
            int task = tid + kk * 256;
            int reg = task >> 10, q2 = task & 1023;
            int r = q2 >> 3, c = q2 & 7;
            const __half* src = (reg == 0)
                ? ab_g + (size_t)(i0 + r) * 256 + s * 64 + c * 8
                : bb_g + (size_t)(c0 + r) * 256 + s * 64 + c * 8;
            CPA(ab + reg * 16384 + r * 128 + 16 * (c ^ (r & 7)), src, 16);
        }
        CPA_COMMIT();
    };
    load(0); load(1);
    for (int s = 0; s < 4; s++) {
        if (s < 3) CPA_WAIT1(); else CPA_WAIT0();
        __syncthreads();
        if (s + 2 < 4) load(s + 2);
        uint32_t ab = smem_b + (s % 3) * 32768;
        mma_stage(acc, ab, ab + 16384, lane, wm, wn);
        __syncthreads();
    }
    __half* outp = g_virt16 + (size_t)loc * 131072;
#pragma unroll
    for (int mf = 0; mf < 4; mf++)
#pragma unroll
        for (int pr = 0; pr < 2; pr++) {
            int i = i0 + wm * 64 + mf * 16 + (lane >> 2) + pr * 8;
            float s = 0.f, sq = 0.f;
#pragma unroll
            for (int nb = 0; nb < 4; nb++) {
                float a0 = acc[mf][nb][pr * 2 + 0];
                float a1 = acc[mf][nb][pr * 2 + 1];
                s += a0 + a1;
                sq += a0 * a0 + a1 * a1;
                int cc = c0 + wn * 32 + nb * 8 + (lane & 3) * 2;
                *(__half2*)&outp[(size_t)i * 512 + cc] = __floats2half2_rn(a0, a1);
            }
            s  += __shfl_xor_sync(0xffffffffu, s, 1);
            s  += __shfl_xor_sync(0xffffffffu, s, 2);
            sq += __shfl_xor_sync(0xffffffffu, sq, 1);
            sq += __shfl_xor_sync(0xffffffffu, sq, 2);
            if ((lane & 3) == 0) {
                atomicAdd(&g_nsum[i], s);
                atomicAdd(&g_nsumsq[i], sq);
            }
        }
}

// ---------------- GroupNorm normalize (+relu) -> fp16 g_vh [loc][n][c] -------------
__global__ __launch_bounds__(256) void gn_norm_kernel(const float* __restrict__ gamma,
                                                      const float* __restrict__ beta) {
    size_t i2 = (size_t)blockIdx.x * 256 + threadIdx.x;
    size_t i = i2 * 2;
    int c = (int)(i & 511);
    int n = (int)((i >> 9) & 255);
    const float inv = 1.f / 131072.f;
    float mu = g_nsum[n] * inv;
    float var = g_nsumsq[n] * inv - mu * mu;
    float rstd = rsqrtf(var + 1e-5f);
    float2 vv = __half22float2(*(const __half2*)&g_virt16[i]);
    float a = fmaxf((vv.x - mu) * rstd * gamma[c] + beta[c], 0.f);
    float b = fmaxf((vv.y - mu) * rstd * gamma[c + 1] + beta[c + 1], 0.f);
    *(__half2*)&g_vh[i] = __floats2half2_rn(a, b);
}

// ---------------- launch ----------------
extern "C" void kernel_launch(void* const* d_in, const int* in_sizes, int n_in,
                              void* d_out, int out_size) {
    const float* x     = (const float*)d_in[0];
    const int*   roi   = (const int*)d_in[1];
    const float* Wq    = (const float*)d_in[2];
    const float* Wk    = (const float*)d_in[3];
    const float* Wv    = (const float*)d_in[4];
    const float* Wc    = (const float*)d_in[5];
    const float* gamma = (const float*)d_in[6];
    const float* beta  = (const float*)d_in[7];
    float* out = (float*)d_out;

    cudaFuncSetAttribute(hconv_qkv_kernel, cudaFuncAttributeMaxDynamicSharedMemorySize, CSM_TOT);
    cudaFuncSetAttribute(hconv_out_kernel, cudaFuncAttributeMaxDynamicSharedMemorySize, CSM_TOT);
    cudaFuncSetAttribute(attn_scores_tc, cudaFuncAttributeMaxDynamicSharedMemorySize, 98304);
    cudaFuncSetAttribute(attn_v_tc, cudaFuncAttributeMaxDynamicSharedMemorySize, 98304);

    pack_x_kernel<<<dim3(8, 1024), 256>>>(x);
    pack_w_kernel<<<36864, 256>>>(Wq, Wk, Wv, Wc);

    hconv_qkv_kernel<<<dim3(512, 12), 256, CSM_TOT>>>();
    vtrans_kernel<<<dim3(32, 256), 256>>>();

    attn_scores_tc<<<dim3(4, 256), 256, 98304>>>(roi);
    softmax_kernel<<<8192, 256>>>();
    attn_v_tc<<<dim3(8, 256), 256, 98304>>>();

    gn_norm_kernel<<<65536, 256>>>(gamma, beta);

    hconv_out_kernel<<<dim3(512, 4), 256, CSM_TOT>>>(x, out);
}

// round 16
// speedup vs baseline: 1.3745x; 1.0058x over previous
#include <cuda_runtime.h>
#include <cuda_fp16.h>
#include <math.h>
#include <stdint.h>

// ---------------- problem constants ----------------
#define C_    512
#define SLAB  131072            // 256*512

// ---------------- device scratch ----------------
__device__ float g_nsum[256];
__device__ float g_nsumsq[256];

__device__ __align__(256) __half g_xh[33554432];    // x fp16 [t][n][pix][ic]
__device__ __align__(256) __half g_vh[33554432];    // v (pre-attn) THEN virt post-GN fp16 [loc][n][c]
__device__ __align__(256) __half g_virt16[33554432];// virt pre-GN fp16 [loc][n][c]
__device__ __align__(256) __half g_qh[33554432];    // q fp16 [loc][n][c]
__device__ __align__(256) __half g_kh[33554432];    // k fp16 [loc][n][c]
__device__ __align__(256) __half g_vT[33554432];    // v fp16 [loc][c][n]
__device__ __align__(256) __half g_att16[16777216]; // softmaxed att fp16 [loc][i][j]
__device__ __align__(256) __half g_wq[7077888];     // [tap][ocp(1536)][ic]
__device__ __align__(256) __half g_wc[2359296];     // [tap][oc][ic]

// ---------------- asm helpers ----------------
__device__ __forceinline__ uint32_t smem_u32_of(const void* p) {
    uint32_t a;
    asm("{ .reg .u64 t; cvta.to.shared.u64 t, %1; cvt.u32.u64 %0, t; }" : "=r"(a) : "l"(p));
    return a;
}
#define CPA(dst, src, sz) \
    asm volatile("cp.async.cg.shared.global [%0], [%1], 16, %2;" \
        :: "r"(dst), "l"(src), "r"(sz) : "memory")
#define CPA_A(dst, src) \
    asm volatile("cp.async.ca.shared.global [%0], [%1], 16;" \
        :: "r"(dst), "l"(src) : "memory")
#define CPA_COMMIT() asm volatile("cp.async.commit_group;" ::: "memory")
#define CPA_WAIT2() asm volatile("cp.async.wait_group 2;" ::: "memory")
#define CPA_WAIT1() asm volatile("cp.async.wait_group 1;" ::: "memory")
#define CPA_WAIT0() asm volatile("cp.async.wait_group 0;" ::: "memory")

__device__ __forceinline__ void ldsm4(uint32_t r[4], uint32_t addr) {
    asm volatile("ldmatrix.sync.aligned.m8n8.x4.shared.b16 {%0,%1,%2,%3}, [%4];"
        : "=r"(r[0]), "=r"(r[1]), "=r"(r[2]), "=r"(r[3]) : "r"(addr));
}
__device__ __forceinline__ void mma16816(float c[4], const uint32_t a[4],
                                         uint32_t b0, uint32_t b1) {
    asm volatile(
        "mma.sync.aligned.m16n8k16.row.col.f32.f16.f16.f32 "
        "{%0,%1,%2,%3}, {%4,%5,%6,%7}, {%8,%9}, {%0,%1,%2,%3};"
        : "+f"(c[0]), "+f"(c[1]), "+f"(c[2]), "+f"(c[3])
        : "r"(a[0]), "r"(a[1]), "r"(a[2]), "r"(a[3]), "r"(b0), "r"(b1));
}

// ---------------- MMA stage (up to 8 warp-columns of 64x32), plain B ----------------
__device__ __forceinline__ void mma_stage(float acc[4][4][4], uint32_t aB, uint32_t bB,
                                          int lane, int wm, int wn) {
#pragma unroll
    for (int ks = 0; ks < 4; ks++) {
        uint32_t Af[4][4];
#pragma unroll
        for (int mf = 0; mf < 4; mf++) {
            int r = wm * 64 + mf * 16 + (lane & 7) + ((lane >> 3) & 1) * 8;
            int kc = ks * 2 + (lane >> 4);
            ldsm4(Af[mf], aB + r * 128 + 16 * (kc ^ (r & 7)));
        }
#pragma unroll
        for (int nb2 = 0; nb2 < 2; nb2++) {
            uint32_t Bf[4];
            int r = wn * 32 + nb2 * 16 + (lane & 7) + ((lane >> 4) << 3);
            int kc = ks * 2 + ((lane >> 3) & 1);
            ldsm4(Bf, bB + r * 128 + 16 * (kc ^ (r & 7)));
#pragma unroll
            for (int mf = 0; mf < 4; mf++) {
                mma16816(acc[mf][nb2 * 2 + 0], Af[mf], Bf[0], Bf[1]);
                mma16816(acc[mf][nb2 * 2 + 1], Af[mf], Bf[2], Bf[3]);
            }
        }
    }
}

// conv variant (64x32 warp tiles): shifted X view (row 128 = zeros)
__device__ __forceinline__ void mma_stage_conv(float acc[4][4][4], uint32_t aB, uint32_t xB,
                                               int lane, int wm, int wn, int dh, int dw) {
#pragma unroll
    for (int ks = 0; ks < 4; ks++) {
        uint32_t Af[4][4];
#pragma unroll
        for (int mf = 0; mf < 4; mf++) {
            int r = wm * 64 + mf * 16 + (lane & 7) + ((lane >> 3) & 1) * 8;
            int kc = ks * 2 + (lane >> 4);
            ldsm4(Af[mf], aB + r * 128 + 16 * (kc ^ (r & 7)));
        }
#pragma unroll
        for (int nb2 = 0; nb2 < 2; nb2++) {
            uint32_t Bf[4];
            int rj = wn * 32 + nb2 * 16 + (lane & 7) + ((lane >> 4) << 3);
            int p = rj & 63, n = rj >> 6;
            int hh = (p >> 3) + dh, ww = (p & 7) + dw;
            bool ok = ((unsigned)hh < 8u) && ((unsigned)ww < 8u);
            int row = ok ? ((n << 6) + (hh << 3) + ww) : 128;
            int kc = ks * 2 + ((lane >> 3) & 1);
            ldsm4(Bf, xB + row * 128 + 16 * (kc ^ (row & 7)));
#pragma unroll
            for (int mf = 0; mf < 4; mf++) {
                mma16816(acc[mf][nb2 * 2 + 0], Af[mf], Bf[0], Bf[1]);
                mma16816(acc[mf][nb2 * 2 + 1], Af[mf], Bf[2], Bf[3]);
            }
        }
    }
}

// ---------------- prepack ----------------
__global__ __launch_bounds__(256) void pack_x_kernel(const float* __restrict__ x) {
    __shared__ float sT[64 * 65];
    int icb = blockIdx.x, nt = blockIdx.y;
    int n = nt >> 2, t = nt & 3;
    int ic0 = icb * 64, tid = threadIdx.x;
#pragma unroll 4
    for (int rep = 0; rep < 16; rep++) {
        int e = rep * 256 + tid;
        int i = e >> 6, p = e & 63;
        sT[i * 65 + p] = x[(((size_t)n * C_ + ic0 + i) * 4 + t) * 64 + p];
    }
    __syncthreads();
#pragma unroll 4
    for (int rep = 0; rep < 16; rep++) {
        int e = rep * 256 + tid;
        int p = e >> 6, i = e & 63;
        g_xh[(size_t)t * 8388608 + (size_t)n * 32768 + (size_t)p * 512 + ic0 + i] =
            __float2half_rn(sT[i * 65 + p]);
    }
}

__global__ __launch_bounds__(256) void pack_w_kernel(const float* __restrict__ wq,
                                                     const float* __restrict__ wk,
                                                     const float* __restrict__ wv,
                                                     const float* __restrict__ wc) {
    int idx = blockIdx.x * 256 + threadIdx.x;
    if (idx < 7077888) {
        int ic = idx & 511, ocp = (idx >> 9) % 1536, tap = idx / (1536 * 512);
        const float* src = (ocp < 512) ? wq : (ocp < 1024) ? wk : wv;
        int oc = ocp & 511;
        g_wq[idx] = __float2half_rn(src[((size_t)oc * 512 + ic) * 9 + tap]);
    } else {
        int j = idx - 7077888;
        if (j < 2359296) {
            int ic = j & 511, oc = (j >> 9) & 511, tap = j >> 18;
            g_wc[j] = __float2half_rn(wc[((size_t)oc * 512 + ic) * 9 + tap]);
        }
    }
}

// ---------------- conv core: A-stream (72 tiles, depth-4) + X-stream (8 tiles) ------
#define CSM_A   0
#define CSM_X   65536
#define CSM_TOT (65536 + 2 * 16640)     // 98816

struct ConvArgs {
    const __half* w; int ocw; int oc0;
    const __half* d; size_t base; int sq; int sn; int n0;
};

__device__ __forceinline__ void conv_core(float acc[4][4][4], const ConvArgs& A_) {
    extern __shared__ char smem[];
    const uint32_t smem_b = smem_u32_of(smem);
    const int tid = threadIdx.x;
    const int lane = tid & 31, wid = tid >> 5;
    const int wm = wid >> 2, wn = wid & 3;

    if (tid < 64) {   // zero halo rows (row 128 of both X buffers)
        int b = tid >> 5, c = tid & 31;
        *(float*)(smem + CSM_X + b * 16640 + 128 * 128 + c * 4) = 0.f;
    }

    auto loadA = [&](int s) {
        int tap = s % 9;
        uint32_t ab = smem_b + CSM_A + (s & 3) * 16384;
#pragma unroll
        for (int kk = 0; kk < 4; kk++) {
            int q = tid + kk * 256;
            int r = q >> 3, c = q & 7;
            const __half* src = A_.w +
                ((size_t)(tap * A_.ocw + A_.oc0 + r)) * 512 + (s / 9) * 64 + c * 8;
            CPA_A(ab + r * 128 + 16 * (c ^ (r & 7)), src);
        }
    };
    auto loadX = [&](int icb) {
        uint32_t xb = smem_b + CSM_X + (icb & 1) * 16640;
#pragma unroll
        for (int kk = 0; kk < 4; kk++) {
            int q = tid + kk * 256;
            int r = q >> 3, c = q & 7;
            int n = A_.n0 + (r >> 6), p = r & 63;
            const __half* src = A_.d + A_.base + (size_t)p * A_.sq +
                (size_t)n * A_.sn + icb * 64 + c * 8;
            CPA(xb + r * 128 + 16 * (c ^ (r & 7)), src, 16);
        }
    };

    loadA(0); loadX(0); CPA_COMMIT();
    loadA(1); CPA_COMMIT();
    loadA(2); CPA_COMMIT();

    for (int s = 0; s < 72; s++) {
        CPA_WAIT2();
        __syncthreads();
        if (s + 3 < 72) loadA(s + 3);
        if ((s % 9) == 0 && (s / 9) < 7) loadX(s / 9 + 1);
        CPA_COMMIT();
        int tap = s % 9;
        mma_stage_conv(acc, smem_b + CSM_A + (s & 3) * 16384,
                       smem_b + CSM_X + ((s / 9) & 1) * 16640,
                       lane, wm, wn, tap / 3 - 1, tap % 3 - 1);
    }
}

// ------- conv qkv: epilogue -> q,k,v ALL coalesced fp16 [loc][n][c] (v into g_vh) ---
__global__ __launch_bounds__(256, 2) void hconv_qkv_kernel() {
    float acc[4][4][4];
#pragma unroll
    for (int a = 0; a < 4; a++)
#pragma unroll
        for (int b = 0; b < 4; b++)
#pragma unroll
            for (int c = 0; c < 4; c++) acc[a][b][c] = 0.f;

    const int mt = blockIdx.y, y = blockIdx.x;     // y 0..511, mt 0..11
    const int t = y >> 7, n0 = (y & 127) * 2;

    ConvArgs ar;
    ar.w = g_wq; ar.ocw = 1536; ar.oc0 = mt * 128;
    ar.d = g_xh; ar.base = (size_t)t * 8388608; ar.sq = 512; ar.sn = 32768; ar.n0 = n0;
    conv_core(acc, ar);

    const int lane = threadIdx.x & 31, wid = threadIdx.x >> 5;
    const int wm = wid >> 2, wn = wid & 3;
    const int kind = mt >> 2;             // 0=q 1=k 2=v
    const int ocb = (mt * 128) & 511;
    __half* dsth = (kind == 0) ? g_qh : (kind == 1) ? g_kh : g_vh;
#pragma unroll
    for (int mf = 0; mf < 4; mf++)
#pragma unroll
        for (int nb = 0; nb < 4; nb++)
#pragma unroll
            for (int pr = 0; pr < 2; pr++) {
                int oc = ocb + wm * 64 + mf * 16 + (lane >> 2) + pr * 8;
#pragma unroll
                for (int e = 0; e < 2; e++) {
                    int j = wn * 32 + nb * 8 + (lane & 3) * 2 + e;
                    int n = n0 + (j >> 6), p = j & 63;
                    size_t loc = (size_t)(t * 64 + p);
                    dsth[loc * 131072 + (size_t)n * 512 + oc] =
                        __float2half_rn(acc[mf][nb][pr * 2 + e]);
                }
            }
}

// -------- v transpose (conflict-free): g_vh [loc][n][c] -> g_vT [loc][c][n] --------
__global__ __launch_bounds__(256) void vtrans_kernel() {
    __shared__ __half sT[64 * 72];
    if (blockIdx.x == 0 && blockIdx.y == 0) {     // zero GN accumulators for attn_v
        g_nsum[threadIdx.x] = 0.f;
        g_nsumsq[threadIdx.x] = 0.f;
    }
    const int loc = blockIdx.y;
    const int n0 = (blockIdx.x & 3) * 64, c0 = (blockIdx.x >> 2) * 64;
    const int tid = threadIdx.x;
#pragma unroll
    for (int pass = 0; pass < 2; pass++) {
        int e = pass * 256 + tid;
        int n = e >> 3, cb = e & 7;               // coalesced gmem read (128B per 8 lanes)
        uint4 u = *(const uint4*)&g_vh[(size_t)loc * 131072 +
                                       (size_t)(n0 + n) * 512 + c0 + cb * 8];
        const __half* h = (const __half*)&u;
#pragma unroll
        for (int i = 0; i < 8; i++) {
            int r = cb * 8 + i;
            sT[r * 72 + (n ^ (cb * 8))] = h[i];   // col-block swizzle by r>>3
        }
    }
    __syncthreads();
#pragma unroll
    for (int pass = 0; pass < 2; pass++) {
        int e = pass * 256 + tid;
        int c = e >> 3, nb = e & 7;               // coalesced gmem write
        int blk = nb ^ (c >> 3);
        uint4 u = *(const uint4*)&sT[c * 72 + blk * 8];
        *(uint4*)&g_vT[(size_t)loc * 131072 + (size_t)(c0 + c) * 256 + n0 + nb * 8] = u;
    }
}

// ---------------- conv out: out = x + conv(vh_postGN, Wc) ----------------
__global__ __launch_bounds__(256, 2) void hconv_out_kernel(const float* __restrict__ x,
                                                           float* __restrict__ out) {
    float acc[4][4][4];
#pragma unroll
    for (int a = 0; a < 4; a++)
#pragma unroll
        for (int b = 0; b < 4; b++)
#pragma unroll
            for (int c = 0; c < 4; c++) acc[a][b][c] = 0.f;

    const int mt = blockIdx.y, y = blockIdx.x;     // y 0..511, mt 0..3
    const int t = y >> 7, n0 = (y & 127) * 2;

    ConvArgs ar;
    ar.w = g_wc; ar.ocw = 512; ar.oc0 = mt * 128;
    ar.d = g_vh; ar.base = (size_t)t * 8388608; ar.sq = 131072; ar.sn = 512; ar.n0 = n0;
    conv_core(acc, ar);

    const int lane = threadIdx.x & 31, wid = threadIdx.x >> 5;
    const int wm = wid >> 2, wn = wid & 3;
    const int oc0 = mt * 128;
#pragma unroll
    for (int mf = 0; mf < 4; mf++)
#pragma unroll
        for (int nb = 0; nb < 4; nb++)
#pragma unroll
            for (int pr = 0; pr < 2; pr++) {
                int oc = oc0 + wm * 64 + mf * 16 + (lane >> 2) + pr * 8;
#pragma unroll
                for (int e = 0; e < 2; e++) {
                    int j = wn * 32 + nb * 8 + (lane & 3) * 2 + e;
                    int n = n0 + (j >> 6), p = j & 63;
                    size_t gi = (((size_t)n * 512 + oc) * 4 + t) * 64 + p;
                    out[gi] = x[gi] + acc[mf][nb][pr * 2 + e];
                }
            }
}

// ------ fused attention scores + softmax: att16 = softmax(mask(scale*q.k^T)) -------
// CTA: 64 i rows x all 256 j, 8 warps of 64x32 (wm=0, wn=wid). 2-stage pipeline.
#define FSM_BUF 40960                   // per stage: Q 8KB @0, K 32KB @8192
#define FSM_RED (2 * FSM_BUF)           // 81920: smax 2KB, ssum 2KB
#define FSM_TOT (FSM_RED + 4096)        // 86016

__global__ __launch_bounds__(256, 2) void attn_sm_tc(const int* __restrict__ roi) {
    float acc[4][4][4];
#pragma unroll
    for (int a = 0; a < 4; a++)
#pragma unroll
        for (int b = 0; b < 4; b++)
#pragma unroll
            for (int c = 0; c < 4; c++) acc[a][b][c] = 0.f;

    extern __shared__ char smem[];
    const uint32_t smem_b = smem_u32_of(smem);
    const int tid = threadIdx.x, lane = tid & 31, wn = tid >> 5;
    const int loc = blockIdx.y;
    const int i0 = blockIdx.x * 64;
    const __half* qb = g_qh + (size_t)loc * 131072;
    const __half* kb = g_kh + (size_t)loc * 131072;

    auto load = [&](int s) {
        uint32_t bb = smem_b + (s & 1) * FSM_BUF;
#pragma unroll
        for (int kk = 0; kk < 10; kk++) {
            int task = tid + kk * 256;
            if (task < 512) {                     // Q tile 64x64
                int r = task >> 3, c = task & 7;
                CPA(bb + r * 128 + 16 * (c ^ (r & 7)),
                    qb + (size_t)(i0 + r) * 512 + s * 64 + c * 8, 16);
            } else {                              // K tile 256x64
                int q2 = task - 512;
                int r = q2 >> 3, c = q2 & 7;
                CPA(bb + 8192 + r * 128 + 16 * (c ^ (r & 7)),
                    kb + (size_t)r * 512 + s * 64 + c * 8, 16);
            }
        }
        CPA_COMMIT();
    };
    load(0); load(1);
    for (int s = 0; s < 8; s++) {
        if (s < 7) CPA_WAIT1(); else CPA_WAIT0();
        __syncthreads();
        uint32_t bb = smem_b + (s & 1) * FSM_BUF;
        mma_stage(acc, bb, bb + 8192, lane, 0, wn);
        __syncthreads();
        if (s + 2 < 8) load(s + 2);
    }

    // ---- mask + scale, then CTA-wide row softmax ----
    const float scale = 0.044194173824159216f;
    float* smax = (float*)(smem + FSM_RED);
    float* ssum = (float*)(smem + FSM_RED + 2048);
    int rj[8];
#pragma unroll
    for (int nb = 0; nb < 4; nb++)
#pragma unroll
        for (int e = 0; e < 2; e++)
            rj[nb * 2 + e] = __ldg(&roi[wn * 32 + nb * 8 + (lane & 3) * 2 + e]);

#pragma unroll
    for (int mf = 0; mf < 4; mf++)
#pragma unroll
        for (int pr = 0; pr < 2; pr++) {
            int row = mf * 16 + (lane >> 2) + pr * 8;
            int ri = __ldg(&roi[i0 + row]);
            float lm = -1e30f;
#pragma unroll
            for (int nb = 0; nb < 4; nb++)
#pragma unroll
                for (int e = 0; e < 2; e++) {
                    float v = (ri == rj[nb * 2 + e])
                        ? acc[mf][nb][pr * 2 + e] * scale : -1e30f;
                    acc[mf][nb][pr * 2 + e] = v;
                    lm = fmaxf(lm, v);
                }
            lm = fmaxf(lm, __shfl_xor_sync(0xffffffffu, lm, 1));
            lm = fmaxf(lm, __shfl_xor_sync(0xffffffffu, lm, 2));
            if ((lane & 3) == 0) smax[wn * 64 + row] = lm;
        }
    __syncthreads();
#pragma unroll
    for (int mf = 0; mf < 4; mf++)
#pragma unroll
        for (int pr = 0; pr < 2; pr++) {
            int row = mf * 16 + (lane >> 2) + pr * 8;
            float m = -1e30f;
#pragma unroll
            for (int w = 0; w < 8; w++) m = fmaxf(m, smax[w * 64 + row]);
            float ls = 0.f;
#pragma unroll
            for (int nb = 0; nb < 4; nb++)
#pragma unroll
                for (int e = 0; e < 2; e++) {
                    float ev = expf(acc[mf][nb][pr * 2 + e] - m);
                    acc[mf][nb][pr * 2 + e] = ev;
                    ls += ev;
                }
            ls += __shfl_xor_sync(0xffffffffu, ls, 1);
            ls += __shfl_xor_sync(0xffffffffu, ls, 2);
            if ((lane & 3) == 0) ssum[wn * 64 + row] = ls;
        }
    __syncthreads();
    __half* outp = g_att16 + (size_t)loc * 65536;
#pragma unroll
    for (int mf = 0; mf < 4; mf++)
#pragma unroll
        for (int pr = 0; pr < 2; pr++) {
            int row = mf * 16 + (lane >> 2) + pr * 8;
            float tot = 0.f;
#pragma unroll
            for (int w = 0; w < 8; w++) tot += ssum[w * 64 + row];
            float inv = 1.f / tot;
            int i = i0 + row;
#pragma unroll
            for (int nb = 0; nb < 4; nb++) {
                int j = wn * 32 + nb * 8 + (lane & 3) * 2;
                *(__half2*)&outp[(size_t)i * 256 + j] = __floats2half2_rn(
                    acc[mf][nb][pr * 2 + 0] * inv, acc[mf][nb][pr * 2 + 1] * inv);
            }
        }
}

// ---------------- virt = att @ v (HMMA) -> g_virt16 fp16 + GN partial sums ----------
__global__ __launch_bounds__(256, 2) void attn_v_tc() {
    float acc[4][4][4];
#pragma unroll
    for (int a = 0; a < 4; a++)
#pragma unroll
        for (int b = 0; b < 4; b++)
#pragma unroll
            for (int c = 0; c < 4; c++) acc[a][b][c] = 0.f;

    extern __shared__ char smem[];
    const uint32_t smem_b = smem_u32_of(smem);
    const int tid = threadIdx.x, lane = tid & 31, wid = tid >> 5;
    const int wm = wid >> 2, wn = wid & 3;
    const int loc = blockIdx.y;
    const int i0 = (blockIdx.x >> 2) * 128, c0 = (blockIdx.x & 3) * 128;
    const __half* ab_g = g_att16 + (size_t)loc * 65536;
    const __half* bb_g = g_vT + (size_t)loc * 131072;

    auto load = [&](int s) {
        uint32_t ab = smem_b + (s % 3) * 32768;
#pragma unroll
        for (int kk = 0; kk < 8; kk++) {
            int task = tid + kk * 256;
            int reg = task >> 10, q2 = task & 1023;
            int r = q2 >> 3, c = q2 & 7;
            const __half* src = (reg == 0)
                ? ab_g + (size_t)(i0 + r) * 256 + s * 64 + c * 8
                : bb_g + (size_t)(c0 + r) * 256 + s * 64 + c * 8;
            CPA(ab + reg * 16384 + r * 128 + 16 * (c ^ (r & 7)), src, 16);
        }
        CPA_COMMIT();
    };
    load(0); load(1);
    for (int s = 0; s < 4; s++) {
        if (s < 3) CPA_WAIT1(); else CPA_WAIT0();
        __syncthreads();
        if (s + 2 < 4) load(s + 2);
        uint32_t ab = smem_b + (s % 3) * 32768;
        mma_stage(acc, ab, ab + 16384, lane, wm, wn);
        __syncthreads();
    }
    __half* outp = g_virt16 + (size_t)loc * 131072;
#pragma unroll
    for (int mf = 0; mf < 4; mf++)
#pragma unroll
        for (int pr = 0; pr < 2; pr++) {
            int i = i0 + wm * 64 + mf * 16 + (lane >> 2) + pr * 8;
            float s = 0.f, sq = 0.f;
#pragma unroll
            for (int nb = 0; nb < 4; nb++) {
                float a0 = acc[mf][nb][pr * 2 + 0];
                float a1 = acc[mf][nb][pr * 2 + 1];
                s += a0 + a1;
                sq += a0 * a0 + a1 * a1;
                int cc = c0 + wn * 32 + nb * 8 + (lane & 3) * 2;
                *(__half2*)&outp[(size_t)i * 512 + cc] = __floats2half2_rn(a0, a1);
            }
            s  += __shfl_xor_sync(0xffffffffu, s, 1);
            s  += __shfl_xor_sync(0xffffffffu, s, 2);
            sq += __shfl_xor_sync(0xffffffffu, sq, 1);
            sq += __shfl_xor_sync(0xffffffffu, sq, 2);
            if ((lane & 3) == 0) {
                atomicAdd(&g_nsum[i], s);
                atomicAdd(&g_nsumsq[i], sq);
            }
        }
}

// ---------------- GroupNorm normalize (+relu) -> fp16 g_vh [loc][n][c] -------------
__global__ __launch_bounds__(256) void gn_norm_kernel(const float* __restrict__ gamma,
                                                      const float* __restrict__ beta) {
    size_t i2 = (size_t)blockIdx.x * 256 + threadIdx.x;
    size_t i = i2 * 2;
    int c = (int)(i & 511);
    int n = (int)((i >> 9) & 255);
    const float inv = 1.f / 131072.f;
    float mu = g_nsum[n] * inv;
    float var = g_nsumsq[n] * inv - mu * mu;
    float rstd = rsqrtf(var + 1e-5f);
    float2 vv = __half22float2(*(const __half2*)&g_virt16[i]);
    float a = fmaxf((vv.x - mu) * rstd * gamma[c] + beta[c], 0.f);
    float b = fmaxf((vv.y - mu) * rstd * gamma[c + 1] + beta[c + 1], 0.f);
    *(__half2*)&g_vh[i] = __floats2half2_rn(a, b);
}

// ---------------- launch ----------------
extern "C" void kernel_launch(void* const* d_in, const int* in_sizes, int n_in,
                              void* d_out, int out_size) {
    const float* x     = (const float*)d_in[0];
    const int*   roi   = (const int*)d_in[1];
    const float* Wq    = (const float*)d_in[2];
    const float* Wk    = (const float*)d_in[3];
    const float* Wv    = (const float*)d_in[4];
    const float* Wc    = (const float*)d_in[5];
    const float* gamma = (const float*)d_in[6];
    const float* beta  = (const float*)d_in[7];
    float* out = (float*)d_out;

    cudaFuncSetAttribute(hconv_qkv_kernel, cudaFuncAttributeMaxDynamicSharedMemorySize, CSM_TOT);
    cudaFuncSetAttribute(hconv_out_kernel, cudaFuncAttributeMaxDynamicSharedMemorySize, CSM_TOT);
    cudaFuncSetAttribute(attn_sm_tc, cudaFuncAttributeMaxDynamicSharedMemorySize, FSM_TOT);
    cudaFuncSetAttribute(attn_v_tc, cudaFuncAttributeMaxDynamicSharedMemorySize, 98304);

    pack_x_kernel<<<dim3(8, 1024), 256>>>(x);
    pack_w_kernel<<<36864, 256>>>(Wq, Wk, Wv, Wc);

    hconv_qkv_kernel<<<dim3(512, 12), 256, CSM_TOT>>>();
    vtrans_kernel<<<dim3(32, 256), 256>>>();

    attn_sm_tc<<<dim3(4, 256), 256, FSM_TOT>>>(roi);
    attn_v_tc<<<dim3(8, 256), 256, 98304>>>();

    gn_norm_kernel<<<65536, 256>>>(gamma, beta);

    hconv_out_kernel<<<dim3(512, 4), 256, CSM_TOT>>>(x, out);
}